// round 3
// baseline (speedup 1.0000x reference)
#include <cuda_runtime.h>

#define FULL 0xffffffffu
typedef unsigned long long ull;

constexpr int   N_SAMP = 64;
constexpr int   RAYS_TOTAL = 4 * 64 * 64;   // 16384
constexpr float NEARF = 2.0f, FARF = 6.0f;
constexpr int   RPB = 8;                    // rays (warps) per block

__device__ __forceinline__ ull pack2(float lo, float hi) {
    ull r; asm("mov.b64 %0,{%1,%2};" : "=l"(r) : "f"(lo), "f"(hi)); return r;
}
__device__ __forceinline__ void unpack2(ull v, float& lo, float& hi) {
    asm("mov.b64 {%0,%1},%2;" : "=f"(lo), "=f"(hi) : "l"(v));
}
__device__ __forceinline__ ull fma2(ull a, ull b, ull c) {
    ull d; asm("fma.rn.f32x2 %0,%1,%2,%3;" : "=l"(d) : "l"(a), "l"(b), "l"(c)); return d;
}
// ReLU on both packed halves; pack/unpack compile to register-pair aliases.
__device__ __forceinline__ ull relu2(ull v) {
    float lo, hi; unpack2(v, lo, hi);
    return pack2(fmaxf(lo, 0.f), fmaxf(hi, 0.f));
}

// # elements < x in sorted a[0..63]
__device__ __forceinline__ int count_lt(const float* __restrict__ a, float x) {
    int lo = 0, hi = 64;
    #pragma unroll
    for (int it = 0; it < 7; ++it) {
        if (lo < hi) { int m = (lo + hi) >> 1; if (a[m] < x) lo = m + 1; else hi = m; }
    }
    return lo;
}
// # elements <= x in sorted a[0..63]
__device__ __forceinline__ int count_le(const float* __restrict__ a, float x) {
    int lo = 0, hi = 64;
    #pragma unroll
    for (int it = 0; it < 7; ++it) {
        if (lo < hi) { int m = (lo + hi) >> 1; if (a[m] <= x) lo = m + 1; else hi = m; }
    }
    return lo;
}

// Tiny MLP at TWO points, fully f32x2-packed.
// W1 arrays (ulonglong2[16]): [q].x = units {4q,4q+1}, [q].y = units {4q+2,4q+3}.
// w2t (ulonglong2[64]): entry 4q+c: .x = {W2[4q][c],W2[4q+1][c]}, .y = {W2[4q+2][c],W2[4q+3][c]}.
// Accumulators stay packed; horizontal add at the end.
__device__ __forceinline__ void field_eval2(
    float px0, float py0, float pz0,
    float px1, float py1, float pz1,
    const ulonglong2* __restrict__ w1a, const ulonglong2* __restrict__ w1b,
    const ulonglong2* __restrict__ w1c, const ulonglong2* __restrict__ bb1,
    const ulonglong2* __restrict__ w2t, float4 b2v,
    float& sg0, float& r0, float& g0, float& b0,
    float& sg1, float& r1, float& g1, float& b1)
{
    const ull X0 = pack2(px0, px0), Y0 = pack2(py0, py0), Z0 = pack2(pz0, pz0);
    const ull X1 = pack2(px1, px1), Y1 = pack2(py1, py1), Z1 = pack2(pz1, pz1);
    ull a00 = pack2(b2v.x, 0.f), a01 = pack2(b2v.y, 0.f);
    ull a02 = pack2(b2v.z, 0.f), a03 = pack2(b2v.w, 0.f);
    ull a10 = pack2(b2v.x, 0.f), a11 = pack2(b2v.y, 0.f);
    ull a12 = pack2(b2v.z, 0.f), a13 = pack2(b2v.w, 0.f);
    #pragma unroll
    for (int q = 0; q < 16; ++q) {
        const ulonglong2 A = w1a[q], Bw = w1b[q], C = w1c[q], D = bb1[q];
        ull h0a = fma2(X0, A.x, fma2(Y0, Bw.x, fma2(Z0, C.x, D.x)));
        ull h0b = fma2(X0, A.y, fma2(Y0, Bw.y, fma2(Z0, C.y, D.y)));
        ull h1a = fma2(X1, A.x, fma2(Y1, Bw.x, fma2(Z1, C.x, D.x)));
        ull h1b = fma2(X1, A.y, fma2(Y1, Bw.y, fma2(Z1, C.y, D.y)));
        h0a = relu2(h0a); h0b = relu2(h0b);
        h1a = relu2(h1a); h1b = relu2(h1b);
        const ulonglong2 T0 = w2t[4 * q + 0], T1 = w2t[4 * q + 1];
        const ulonglong2 T2 = w2t[4 * q + 2], T3 = w2t[4 * q + 3];
        a00 = fma2(h0a, T0.x, a00); a00 = fma2(h0b, T0.y, a00);
        a01 = fma2(h0a, T1.x, a01); a01 = fma2(h0b, T1.y, a01);
        a02 = fma2(h0a, T2.x, a02); a02 = fma2(h0b, T2.y, a02);
        a03 = fma2(h0a, T3.x, a03); a03 = fma2(h0b, T3.y, a03);
        a10 = fma2(h1a, T0.x, a10); a10 = fma2(h1b, T0.y, a10);
        a11 = fma2(h1a, T1.x, a11); a11 = fma2(h1b, T1.y, a11);
        a12 = fma2(h1a, T2.x, a12); a12 = fma2(h1b, T2.y, a12);
        a13 = fma2(h1a, T3.x, a13); a13 = fma2(h1b, T3.y, a13);
    }
    float lo, hi;
    unpack2(a00, lo, hi); sg0 = lo + hi;
    unpack2(a01, lo, hi); r0 = __fdividef(1.f, 1.f + __expf(-(lo + hi)));
    unpack2(a02, lo, hi); g0 = __fdividef(1.f, 1.f + __expf(-(lo + hi)));
    unpack2(a03, lo, hi); b0 = __fdividef(1.f, 1.f + __expf(-(lo + hi)));
    unpack2(a10, lo, hi); sg1 = lo + hi;
    unpack2(a11, lo, hi); r1 = __fdividef(1.f, 1.f + __expf(-(lo + hi)));
    unpack2(a12, lo, hi); g1 = __fdividef(1.f, 1.f + __expf(-(lo + hi)));
    unpack2(a13, lo, hi); b1 = __fdividef(1.f, 1.f + __expf(-(lo + hi)));
}

__global__ void __launch_bounds__(RPB * 32, 4)
nerf_kernel(const float* __restrict__ ro,   const float* __restrict__ rdi,
            const float* __restrict__ tform, const float* __restrict__ noise,
            const float* __restrict__ usmp,
            const float* __restrict__ gW1, const float* __restrict__ gb1,
            const float* __restrict__ gW2, const float* __restrict__ gb2,
            float* __restrict__ orgb, float* __restrict__ odep, float* __restrict__ omsk)
{
    __shared__ float4 sW1a[16], sW1b[16], sW1c[16], sB1[16];
    __shared__ ulonglong2 sW2t[64];
    __shared__ float  sB2[4];
    __shared__ float  sZ [RPB][128];   // coarse z [0..63], then all-sorted z
    __shared__ float  sSg[RPB][128];   // cdf [0..62], sorted fine [64..127], then sorted sigma
    __shared__ float  sC [RPB][384];   // sorted rgb
    __shared__ float  sWt[RPB][64];    // coarse compositing weights

    const int tid = threadIdx.x;
    if (tid < 64) {
        ((float*)sW1a)[tid] = gW1[tid];
        ((float*)sW1b)[tid] = gW1[64 + tid];
        ((float*)sW1c)[tid] = gW1[128 + tid];
        ((float*)sB1)[tid]  = gb1[tid];
    }
    if (tid < 128) {
        // transposed pair-packed W2
        const int e = tid >> 1, half = tid & 1;
        const int q = e >> 2, c = e & 3;
        const int u0 = 4 * q + 2 * half;
        ((ull*)sW2t)[tid] = pack2(gW2[u0 * 4 + c], gW2[(u0 + 1) * 4 + c]);
    }
    if (tid < 4) sB2[tid] = gb2[tid];
    __syncthreads();

    const ulonglong2* w1a2 = (const ulonglong2*)sW1a;
    const ulonglong2* w1b2 = (const ulonglong2*)sW1b;
    const ulonglong2* w1c2 = (const ulonglong2*)sW1c;
    const ulonglong2* bb12 = (const ulonglong2*)sB1;
    const float4 b2v = make_float4(sB2[0], sB2[1], sB2[2], sB2[3]);

    const int wrp = tid >> 5, lane = tid & 31;
    const int ray = blockIdx.x * RPB + wrp;
    float* zw  = sZ[wrp];
    float* sgw = sSg[wrp];
    float* sf  = sgw + 64;     // sorted fine z
    float* cw  = sC[wrp];
    float* wtw = sWt[wrp];

    const int bidx = ray >> 12;

    const float ox = ro[ray * 3 + 0], oy = ro[ray * 3 + 1], oz = ro[ray * 3 + 2];
    float dx = rdi[ray * 3 + 0], dy = rdi[ray * 3 + 1], dz = rdi[ray * 3 + 2];
    const float rinvn = rsqrtf(dx * dx + dy * dy + dz * dz);
    dx *= rinvn; dy *= rinvn; dz *= rinvn;

    // -------- coarse stratified z (sorted by construction) --------
    const float2 nzp = ((const float2*)(noise + ray * N_SAMP))[lane];
    const int i0 = 2 * lane, i1 = i0 + 1;
    const float z0 = NEARF + (FARF - NEARF) * (((float)i0 + nzp.x) * (1.f / 64.f));
    const float z1 = NEARF + (FARF - NEARF) * (((float)i1 + nzp.y) * (1.f / 64.f));
    zw[i0] = z0; zw[i1] = z1;
    __syncwarp();

    // -------- coarse MLP --------
    float sg0, cr0, cg0, cb0, sg1, cr1, cg1, cb1;
    field_eval2(fmaf(dx, z0, ox), fmaf(dy, z0, oy), fmaf(dz, z0, oz),
                fmaf(dx, z1, ox), fmaf(dy, z1, oy), fmaf(dz, z1, oz),
                w1a2, w1b2, w1c2, bb12, sW2t, b2v,
                sg0, cr0, cg0, cb0, sg1, cr1, cg1, cb1);

    // -------- coarse compositing weights (warp multiplicative scan) --------
    const float d0 = z1 - z0;
    const float znx = (lane < 31) ? zw[i1 + 1] : 0.f;
    const float d1 = (lane == 31) ? 1e10f : (znx - z1);
    const float e0 = __expf(-fmaxf(sg0, 0.f) * d0);
    const float e1 = __expf(-fmaxf(sg1, 0.f) * d1);
    const float a0 = 1.f - e0, a1 = 1.f - e1;
    const float m0 = 1.f - a0 + 1e-10f, m1 = 1.f - a1 + 1e-10f;
    {
        float v = m0 * m1;
        #pragma unroll
        for (int off = 1; off < 32; off <<= 1) {
            float t = __shfl_up_sync(FULL, v, off);
            if (lane >= off) v *= t;
        }
        float ex = __shfl_up_sync(FULL, v, 1);
        if (lane == 0) ex = 1.f;
        wtw[i0] = a0 * ex;
        wtw[i1] = a1 * ex * m0;
    }
    __syncwarp();

    // -------- pooled pdf -> cdf (63 entries in sgw[0..62]) --------
    {
        float s1 = 0.f, s2 = 0.f;
        if (lane < 31) {
            const int ii = 2 * lane + 1;
            const float wm = wtw[ii - 1], wc = wtw[ii], wp = wtw[ii + 1], wq = wtw[ii + 2];
            s1 = 0.5f * (fmaxf(wm, wc) + fmaxf(wc, wp)) + 0.01f;
            s2 = 0.5f * (fmaxf(wc, wp) + fmaxf(wp, wq)) + 0.01f;
        }
        const float pr = s1 + s2;
        float v = pr;
        #pragma unroll
        for (int off = 1; off < 32; off <<= 1) {
            float t = __shfl_up_sync(FULL, v, off);
            if (lane >= off) v += t;
        }
        const float tot = __shfl_sync(FULL, v, 30);
        const float rv = __fdividef(1.f, tot);
        const float ex = v - pr;
        if (lane == 0) sgw[0] = 0.f;
        if (lane < 31) {
            sgw[2 * lane + 1] = (ex + s1) * rv;
            sgw[2 * lane + 2] = v * rv;
        }
    }
    __syncwarp();

    // -------- inverse-CDF fine samples (2 per lane, unsorted) --------
    const float* uu = usmp + ray * N_SAMP;
    float zs0 = 0.f, zs1 = 0.f;
    #pragma unroll
    for (int k = 0; k < 2; ++k) {
        const float u = uu[lane + 32 * k];
        int lo = 0, hi = 63;                       // searchsorted(cdf[0..62], u, right)
        while (lo < hi) {
            const int mid = (lo + hi) >> 1;
            if (sgw[mid] <= u) lo = mid + 1; else hi = mid;
        }
        const int below = lo - 1;
        const int above = lo < 62 ? lo : 62;
        const float cbv = sgw[below], cav = sgw[above];
        float den = cav - cbv;
        if (den < 1e-5f) den = 1.f;
        const float t  = __fdividef(u - cbv, den);
        const float bb = 0.5f * (zw[below] + zw[below + 1]);
        const float ba = 0.5f * (zw[above] + zw[above + 1]);
        const float zz = fmaf(t, ba - bb, bb);
        if (k == 0) zs0 = zz; else zs1 = zz;
    }

    // -------- bitonic sort of the 64 fine samples (registers + shfl) --------
    float v0 = zs0, v1 = zs1;
    {
        const int e0l = lane, e1l = lane + 32;
        #pragma unroll
        for (int k = 2; k <= 64; k <<= 1) {
            #pragma unroll
            for (int j = k >> 1; j >= 1; j >>= 1) {
                if (j == 32) {
                    const float lo = fminf(v0, v1), hi = fmaxf(v0, v1);
                    v0 = lo; v1 = hi;
                } else {
                    const float t0 = __shfl_xor_sync(FULL, v0, j);
                    const bool keep0 = (((e0l & k) == 0) == ((e0l & j) == 0));
                    v0 = keep0 ? fminf(v0, t0) : fmaxf(v0, t0);
                    const float t1 = __shfl_xor_sync(FULL, v1, j);
                    const bool keep1 = (((e1l & k) == 0) == ((e1l & j) == 0));
                    v1 = keep1 ? fminf(v1, t1) : fmaxf(v1, t1);
                }
            }
        }
    }
    __syncwarp();                                  // cdf reads done before sf write
    sf[lane] = v0;
    sf[lane + 32] = v1;

    // -------- fine MLP at SORTED fine positions --------
    float fs0, fr0, fg0, fb0, fs1, fr1, fg1, fb1;
    field_eval2(fmaf(dx, v0, ox), fmaf(dy, v0, oy), fmaf(dz, v0, oz),
                fmaf(dx, v1, ox), fmaf(dy, v1, oy), fmaf(dz, v1, oz),
                w1a2, w1b2, w1c2, bb12, sW2t, b2v,
                fs0, fr0, fg0, fb0, fs1, fr1, fg1, fb1);
    __syncwarp();                                  // sf fully written

    // -------- merge ranks: coarse sorted x fine sorted --------
    const int r0 = i0 + count_lt(sf, z0);          // ties: coarse first
    const int r1 = i1 + count_lt(sf, z1);
    const int r2 = lane      + count_le(zw, v0);   // ties: fine after coarse
    const int r3 = lane + 32 + count_le(zw, v1);
    __syncwarp();                                  // all reads done before scatter

    zw[r0] = z0; sgw[r0] = sg0; cw[3 * r0] = cr0; cw[3 * r0 + 1] = cg0; cw[3 * r0 + 2] = cb0;
    zw[r1] = z1; sgw[r1] = sg1; cw[3 * r1] = cr1; cw[3 * r1 + 1] = cg1; cw[3 * r1 + 2] = cb1;
    zw[r2] = v0; sgw[r2] = fs0; cw[3 * r2] = fr0; cw[3 * r2 + 1] = fg0; cw[3 * r2 + 2] = fb0;
    zw[r3] = v1; sgw[r3] = fs1; cw[3 * r3] = fr1; cw[3 * r3 + 1] = fg1; cw[3 * r3 + 2] = fb1;
    __syncwarp();

    // -------- final compositing over 128 sorted samples (4 per lane) --------
    const int p = 4 * lane;
    const float za = zw[p], zb = zw[p + 1], zc = zw[p + 2], zd = zw[p + 3];
    const float zn = (lane < 31) ? zw[p + 4] : 0.f;
    const float sa = sgw[p], sb = sgw[p + 1], sc = sgw[p + 2], sd = sgw[p + 3];
    const float dda = zb - za, ddb = zc - zb, ddc = zd - zc;
    const float ddd = (lane == 31) ? 1e10f : (zn - zd);
    const float ea2 = __expf(-fmaxf(sa, 0.f) * dda);
    const float eb2 = __expf(-fmaxf(sb, 0.f) * ddb);
    const float ec2 = __expf(-fmaxf(sc, 0.f) * ddc);
    const float ed2 = __expf(-fmaxf(sd, 0.f) * ddd);
    const float aa = 1.f - ea2, ab = 1.f - eb2, ac = 1.f - ec2, ad = 1.f - ed2;
    const float ma = 1.f - aa + 1e-10f, mb = 1.f - ab + 1e-10f;
    const float mc = 1.f - ac + 1e-10f, md = 1.f - ad + 1e-10f;
    const float q0 = ma, q1 = ma * mb, q2 = q1 * mc, q3 = q2 * md;
    float v = q3;
    #pragma unroll
    for (int off = 1; off < 32; off <<= 1) {
        float t = __shfl_up_sync(FULL, v, off);
        if (lane >= off) v *= t;
    }
    float E = __shfl_up_sync(FULL, v, 1);
    if (lane == 0) E = 1.f;
    const float wA = aa * E, wB = ab * E * q0, wC = ac * E * q1, wD = ad * E * q2;

    float SW = wA + wB + wC + wD;
    float SZ = wA * za + wB * zb + wC * zc + wD * zd;
    float SR = wA * cw[3 * p]     + wB * cw[3 * (p + 1)]     + wC * cw[3 * (p + 2)]     + wD * cw[3 * (p + 3)];
    float SG = wA * cw[3 * p + 1] + wB * cw[3 * (p + 1) + 1] + wC * cw[3 * (p + 2) + 1] + wD * cw[3 * (p + 3) + 1];
    float SB = wA * cw[3 * p + 2] + wB * cw[3 * (p + 1) + 2] + wC * cw[3 * (p + 2) + 2] + wD * cw[3 * (p + 3) + 2];

    #pragma unroll
    for (int off = 16; off; off >>= 1) {
        SW += __shfl_xor_sync(FULL, SW, off);
        SZ += __shfl_xor_sync(FULL, SZ, off);
        SR += __shfl_xor_sync(FULL, SR, off);
        SG += __shfl_xor_sync(FULL, SG, off);
        SB += __shfl_xor_sync(FULL, SB, off);
    }

    if (lane == 0) {
        orgb[ray * 3 + 0] = SR;
        orgb[ray * 3 + 1] = SG;
        orgb[ray * 3 + 2] = SB;
        const float* Tm = tform + bidx * 16;
        const float vz = dx * Tm[2] + dy * Tm[6] + dz * Tm[10];
        odep[ray] = -vz * SZ;
        omsk[ray] = SW;
    }
}

extern "C" void kernel_launch(void* const* d_in, const int* in_sizes, int n_in,
                              void* d_out, int out_size)
{
    const float* ro    = (const float*)d_in[0];
    const float* rdi   = (const float*)d_in[1];
    const float* tform = (const float*)d_in[2];
    const float* noise = (const float*)d_in[3];
    const float* usmp  = (const float*)d_in[4];
    const float* W1    = (const float*)d_in[5];
    const float* b1    = (const float*)d_in[6];
    const float* W2    = (const float*)d_in[7];
    const float* b2    = (const float*)d_in[8];

    float* out = (float*)d_out;
    float* orgb = out;
    float* odep = out + RAYS_TOTAL * 3;
    float* omsk = odep + RAYS_TOTAL;

    dim3 grid(RAYS_TOTAL / RPB);
    dim3 block(RPB * 32);
    nerf_kernel<<<grid, block>>>(ro, rdi, tform, noise, usmp, W1, b1, W2, b2,
                                 orgb, odep, omsk);
}

// round 4
// speedup vs baseline: 1.1149x; 1.1149x over previous
#include <cuda_runtime.h>

#define FULL 0xffffffffu
typedef unsigned long long ull;

constexpr int   N_SAMP = 64;
constexpr int   RAYS_TOTAL = 4 * 64 * 64;   // 16384
constexpr float NEARF = 2.0f, FARF = 6.0f;
constexpr int   RPB = 8;                    // rays (warps) per block

__device__ __forceinline__ ull pack2(float lo, float hi) {
    ull r; asm("mov.b64 %0,{%1,%2};" : "=l"(r) : "f"(lo), "f"(hi)); return r;
}
__device__ __forceinline__ void unpack2(ull v, float& lo, float& hi) {
    asm("mov.b64 {%0,%1},%2;" : "=f"(lo), "=f"(hi) : "l"(v));
}
__device__ __forceinline__ ull fma2(ull a, ull b, ull c) {
    ull d; asm("fma.rn.f32x2 %0,%1,%2,%3;" : "=l"(d) : "l"(a), "l"(b), "l"(c)); return d;
}
__device__ __forceinline__ ull relu2(ull v) {
    float lo, hi; unpack2(v, lo, hi);
    return pack2(fmaxf(lo, 0.f), fmaxf(hi, 0.f));
}

// ---- weights in constant memory (filled by pack_weights + memcpyToSymbol) ----
// layout (ulonglong2 units):
//   [0..15]   w1a : W1 row-x natural pair packing ([q].x = units{4q,4q+1}, .y = {4q+2,4q+3})
//   [16..31]  w1b : W1 row-y
//   [32..47]  w1c : W1 row-z
//   [48..63]  bb1 : b1
//   [64..127] w2t : entry 4q+c: .x = {W2[4q][c],W2[4q+1][c]}, .y = {W2[4q+2][c],W2[4q+3][c]}
//   [128]     b2  : {(b2_0,b2_1),(b2_2,b2_3)}
__constant__ ulonglong2 cAll[129];
__device__   ulonglong2 g_stage[129];

__global__ void pack_weights(const float* __restrict__ W1, const float* __restrict__ b1f,
                             const float* __restrict__ W2, const float* __restrict__ b2f)
{
    const int t = threadIdx.x;   // 0..63
    float* s = (float*)g_stage;
    s[t]       = W1[t];          // row x  -> floats [0..63]
    s[64 + t]  = W1[64 + t];     // row y  -> [64..127]
    s[128 + t] = W1[128 + t];    // row z  -> [128..191]
    s[192 + t] = b1f[t];         // b1     -> [192..255]
    // w2t: 128 ull entries at ull offset 128 (float offset 256)
    ull* w2t = ((ull*)g_stage) + 128;
    int e = t;
    #pragma unroll
    for (int k = 0; k < 2; ++k, e += 64) {
        const int ent = e >> 1, half = e & 1;   // ent = 4q+c
        const int q = ent >> 2, c = ent & 3;
        const int u0 = 4 * q + 2 * half;
        w2t[e] = pack2(W2[u0 * 4 + c], W2[(u0 + 1) * 4 + c]);
    }
    if (t == 0) {
        s[512] = b2f[0]; s[513] = b2f[1]; s[514] = b2f[2]; s[515] = b2f[3];
    }
}

// # elements < x in sorted a[0..63]
__device__ __forceinline__ int count_lt(const float* __restrict__ a, float x) {
    int lo = 0, hi = 64;
    #pragma unroll
    for (int it = 0; it < 7; ++it) {
        if (lo < hi) { int m = (lo + hi) >> 1; if (a[m] < x) lo = m + 1; else hi = m; }
    }
    return lo;
}
// # elements <= x in sorted a[0..63]
__device__ __forceinline__ int count_le(const float* __restrict__ a, float x) {
    int lo = 0, hi = 64;
    #pragma unroll
    for (int it = 0; it < 7; ++it) {
        if (lo < hi) { int m = (lo + hi) >> 1; if (a[m] <= x) lo = m + 1; else hi = m; }
    }
    return lo;
}

// Tiny MLP at TWO points, fully f32x2-packed, weights from __constant__.
__device__ __forceinline__ void field_eval2(
    float px0, float py0, float pz0,
    float px1, float py1, float pz1,
    float4 b2v,
    float& sg0, float& r0, float& g0, float& b0,
    float& sg1, float& r1, float& g1, float& b1)
{
    const ulonglong2* __restrict__ w1a = cAll;
    const ulonglong2* __restrict__ w1b = cAll + 16;
    const ulonglong2* __restrict__ w1c = cAll + 32;
    const ulonglong2* __restrict__ bb1 = cAll + 48;
    const ulonglong2* __restrict__ w2t = cAll + 64;

    const ull X0 = pack2(px0, px0), Y0 = pack2(py0, py0), Z0 = pack2(pz0, pz0);
    const ull X1 = pack2(px1, px1), Y1 = pack2(py1, py1), Z1 = pack2(pz1, pz1);
    ull a00 = pack2(b2v.x, 0.f), a01 = pack2(b2v.y, 0.f);
    ull a02 = pack2(b2v.z, 0.f), a03 = pack2(b2v.w, 0.f);
    ull a10 = pack2(b2v.x, 0.f), a11 = pack2(b2v.y, 0.f);
    ull a12 = pack2(b2v.z, 0.f), a13 = pack2(b2v.w, 0.f);
    #pragma unroll
    for (int q = 0; q < 16; ++q) {
        const ulonglong2 A = w1a[q], Bw = w1b[q], C = w1c[q], D = bb1[q];
        ull h0a = fma2(X0, A.x, fma2(Y0, Bw.x, fma2(Z0, C.x, D.x)));
        ull h0b = fma2(X0, A.y, fma2(Y0, Bw.y, fma2(Z0, C.y, D.y)));
        ull h1a = fma2(X1, A.x, fma2(Y1, Bw.x, fma2(Z1, C.x, D.x)));
        ull h1b = fma2(X1, A.y, fma2(Y1, Bw.y, fma2(Z1, C.y, D.y)));
        h0a = relu2(h0a); h0b = relu2(h0b);
        h1a = relu2(h1a); h1b = relu2(h1b);
        const ulonglong2 T0 = w2t[4 * q + 0], T1 = w2t[4 * q + 1];
        const ulonglong2 T2 = w2t[4 * q + 2], T3 = w2t[4 * q + 3];
        a00 = fma2(h0a, T0.x, a00); a00 = fma2(h0b, T0.y, a00);
        a01 = fma2(h0a, T1.x, a01); a01 = fma2(h0b, T1.y, a01);
        a02 = fma2(h0a, T2.x, a02); a02 = fma2(h0b, T2.y, a02);
        a03 = fma2(h0a, T3.x, a03); a03 = fma2(h0b, T3.y, a03);
        a10 = fma2(h1a, T0.x, a10); a10 = fma2(h1b, T0.y, a10);
        a11 = fma2(h1a, T1.x, a11); a11 = fma2(h1b, T1.y, a11);
        a12 = fma2(h1a, T2.x, a12); a12 = fma2(h1b, T2.y, a12);
        a13 = fma2(h1a, T3.x, a13); a13 = fma2(h1b, T3.y, a13);
    }
    float lo, hi;
    unpack2(a00, lo, hi); sg0 = lo + hi;
    unpack2(a01, lo, hi); r0 = __fdividef(1.f, 1.f + __expf(-(lo + hi)));
    unpack2(a02, lo, hi); g0 = __fdividef(1.f, 1.f + __expf(-(lo + hi)));
    unpack2(a03, lo, hi); b0 = __fdividef(1.f, 1.f + __expf(-(lo + hi)));
    unpack2(a10, lo, hi); sg1 = lo + hi;
    unpack2(a11, lo, hi); r1 = __fdividef(1.f, 1.f + __expf(-(lo + hi)));
    unpack2(a12, lo, hi); g1 = __fdividef(1.f, 1.f + __expf(-(lo + hi)));
    unpack2(a13, lo, hi); b1 = __fdividef(1.f, 1.f + __expf(-(lo + hi)));
}

__global__ void __launch_bounds__(RPB * 32, 4)
nerf_kernel(const float* __restrict__ ro,   const float* __restrict__ rdi,
            const float* __restrict__ tform, const float* __restrict__ noise,
            const float* __restrict__ usmp,
            float* __restrict__ orgb, float* __restrict__ odep, float* __restrict__ omsk)
{
    __shared__ float  sZ [RPB][128];   // coarse z [0..63], then all-sorted z
    __shared__ float  sSg[RPB][128];   // cdf [0..62], sorted fine [64..127], then sorted sigma
    __shared__ float  sC [RPB][384];   // sorted rgb
    __shared__ float  sWt[RPB][64];    // coarse compositing weights

    const int tid = threadIdx.x;
    const int wrp = tid >> 5, lane = tid & 31;
    const int ray = blockIdx.x * RPB + wrp;
    float* zw  = sZ[wrp];
    float* sgw = sSg[wrp];
    float* sf  = sgw + 64;     // sorted fine z
    float* cw  = sC[wrp];
    float* wtw = sWt[wrp];

    float b20, b21, b22, b23;
    unpack2(cAll[128].x, b20, b21);
    unpack2(cAll[128].y, b22, b23);
    const float4 b2v = make_float4(b20, b21, b22, b23);

    const int bidx = ray >> 12;

    const float ox = ro[ray * 3 + 0], oy = ro[ray * 3 + 1], oz = ro[ray * 3 + 2];
    float dx = rdi[ray * 3 + 0], dy = rdi[ray * 3 + 1], dz = rdi[ray * 3 + 2];
    const float rinvn = rsqrtf(dx * dx + dy * dy + dz * dz);
    dx *= rinvn; dy *= rinvn; dz *= rinvn;

    // -------- coarse stratified z (sorted by construction) --------
    const float2 nzp = ((const float2*)(noise + ray * N_SAMP))[lane];
    const int i0 = 2 * lane, i1 = i0 + 1;
    const float z0 = NEARF + (FARF - NEARF) * (((float)i0 + nzp.x) * (1.f / 64.f));
    const float z1 = NEARF + (FARF - NEARF) * (((float)i1 + nzp.y) * (1.f / 64.f));
    zw[i0] = z0; zw[i1] = z1;
    __syncwarp();

    // -------- coarse MLP --------
    float sg0, cr0, cg0, cb0, sg1, cr1, cg1, cb1;
    field_eval2(fmaf(dx, z0, ox), fmaf(dy, z0, oy), fmaf(dz, z0, oz),
                fmaf(dx, z1, ox), fmaf(dy, z1, oy), fmaf(dz, z1, oz),
                b2v, sg0, cr0, cg0, cb0, sg1, cr1, cg1, cb1);

    // -------- coarse compositing weights (warp multiplicative scan) --------
    const float d0 = z1 - z0;
    const float znx = (lane < 31) ? zw[i1 + 1] : 0.f;
    const float d1 = (lane == 31) ? 1e10f : (znx - z1);
    const float e0 = __expf(-fmaxf(sg0, 0.f) * d0);
    const float e1 = __expf(-fmaxf(sg1, 0.f) * d1);
    const float a0 = 1.f - e0, a1 = 1.f - e1;
    const float m0 = 1.f - a0 + 1e-10f, m1 = 1.f - a1 + 1e-10f;
    {
        float v = m0 * m1;
        #pragma unroll
        for (int off = 1; off < 32; off <<= 1) {
            float t = __shfl_up_sync(FULL, v, off);
            if (lane >= off) v *= t;
        }
        float ex = __shfl_up_sync(FULL, v, 1);
        if (lane == 0) ex = 1.f;
        wtw[i0] = a0 * ex;
        wtw[i1] = a1 * ex * m0;
    }
    __syncwarp();

    // -------- pooled pdf -> cdf (63 entries in sgw[0..62]) --------
    {
        float s1 = 0.f, s2 = 0.f;
        if (lane < 31) {
            const int ii = 2 * lane + 1;
            const float wm = wtw[ii - 1], wc = wtw[ii], wp = wtw[ii + 1], wq = wtw[ii + 2];
            s1 = 0.5f * (fmaxf(wm, wc) + fmaxf(wc, wp)) + 0.01f;
            s2 = 0.5f * (fmaxf(wc, wp) + fmaxf(wp, wq)) + 0.01f;
        }
        const float pr = s1 + s2;
        float v = pr;
        #pragma unroll
        for (int off = 1; off < 32; off <<= 1) {
            float t = __shfl_up_sync(FULL, v, off);
            if (lane >= off) v += t;
        }
        const float tot = __shfl_sync(FULL, v, 30);
        const float rv = __fdividef(1.f, tot);
        const float ex = v - pr;
        if (lane == 0) sgw[0] = 0.f;
        if (lane < 31) {
            sgw[2 * lane + 1] = (ex + s1) * rv;
            sgw[2 * lane + 2] = v * rv;
        }
    }
    __syncwarp();

    // -------- inverse-CDF fine samples (2 per lane, unsorted) --------
    const float* uu = usmp + ray * N_SAMP;
    float zs0 = 0.f, zs1 = 0.f;
    #pragma unroll
    for (int k = 0; k < 2; ++k) {
        const float u = uu[lane + 32 * k];
        int lo = 0, hi = 63;                       // searchsorted(cdf[0..62], u, right)
        while (lo < hi) {
            const int mid = (lo + hi) >> 1;
            if (sgw[mid] <= u) lo = mid + 1; else hi = mid;
        }
        const int below = lo - 1;
        const int above = lo < 62 ? lo : 62;
        const float cbv = sgw[below], cav = sgw[above];
        float den = cav - cbv;
        if (den < 1e-5f) den = 1.f;
        const float t  = __fdividef(u - cbv, den);
        const float bb = 0.5f * (zw[below] + zw[below + 1]);
        const float ba = 0.5f * (zw[above] + zw[above + 1]);
        const float zz = fmaf(t, ba - bb, bb);
        if (k == 0) zs0 = zz; else zs1 = zz;
    }

    // -------- bitonic sort of the 64 fine samples (registers + shfl) --------
    float v0 = zs0, v1 = zs1;
    {
        const int e0l = lane, e1l = lane + 32;
        #pragma unroll
        for (int k = 2; k <= 64; k <<= 1) {
            #pragma unroll
            for (int j = k >> 1; j >= 1; j >>= 1) {
                if (j == 32) {
                    const float lo = fminf(v0, v1), hi = fmaxf(v0, v1);
                    v0 = lo; v1 = hi;
                } else {
                    const float t0 = __shfl_xor_sync(FULL, v0, j);
                    const bool keep0 = (((e0l & k) == 0) == ((e0l & j) == 0));
                    v0 = keep0 ? fminf(v0, t0) : fmaxf(v0, t0);
                    const float t1 = __shfl_xor_sync(FULL, v1, j);
                    const bool keep1 = (((e1l & k) == 0) == ((e1l & j) == 0));
                    v1 = keep1 ? fminf(v1, t1) : fmaxf(v1, t1);
                }
            }
        }
    }
    __syncwarp();                                  // cdf reads done before sf write
    sf[lane] = v0;
    sf[lane + 32] = v1;

    // -------- fine MLP at SORTED fine positions --------
    float fs0, fr0, fg0, fb0, fs1, fr1, fg1, fb1;
    field_eval2(fmaf(dx, v0, ox), fmaf(dy, v0, oy), fmaf(dz, v0, oz),
                fmaf(dx, v1, ox), fmaf(dy, v1, oy), fmaf(dz, v1, oz),
                b2v, fs0, fr0, fg0, fb0, fs1, fr1, fg1, fb1);
    __syncwarp();                                  // sf fully written

    // -------- merge ranks: coarse sorted x fine sorted --------
    const int r0 = i0 + count_lt(sf, z0);          // ties: coarse first
    const int r1 = i1 + count_lt(sf, z1);
    const int r2 = lane      + count_le(zw, v0);   // ties: fine after coarse
    const int r3 = lane + 32 + count_le(zw, v1);
    __syncwarp();                                  // all reads done before scatter

    zw[r0] = z0; sgw[r0] = sg0; cw[3 * r0] = cr0; cw[3 * r0 + 1] = cg0; cw[3 * r0 + 2] = cb0;
    zw[r1] = z1; sgw[r1] = sg1; cw[3 * r1] = cr1; cw[3 * r1 + 1] = cg1; cw[3 * r1 + 2] = cb1;
    zw[r2] = v0; sgw[r2] = fs0; cw[3 * r2] = fr0; cw[3 * r2 + 1] = fg0; cw[3 * r2 + 2] = fb0;
    zw[r3] = v1; sgw[r3] = fs1; cw[3 * r3] = fr1; cw[3 * r3 + 1] = fg1; cw[3 * r3 + 2] = fb1;
    __syncwarp();

    // -------- final compositing over 128 sorted samples (4 per lane) --------
    const int p = 4 * lane;
    const float za = zw[p], zb = zw[p + 1], zc = zw[p + 2], zd = zw[p + 3];
    const float zn = (lane < 31) ? zw[p + 4] : 0.f;
    const float sa = sgw[p], sb = sgw[p + 1], sc = sgw[p + 2], sd = sgw[p + 3];
    const float dda = zb - za, ddb = zc - zb, ddc = zd - zc;
    const float ddd = (lane == 31) ? 1e10f : (zn - zd);
    const float ea2 = __expf(-fmaxf(sa, 0.f) * dda);
    const float eb2 = __expf(-fmaxf(sb, 0.f) * ddb);
    const float ec2 = __expf(-fmaxf(sc, 0.f) * ddc);
    const float ed2 = __expf(-fmaxf(sd, 0.f) * ddd);
    const float aa = 1.f - ea2, ab = 1.f - eb2, ac = 1.f - ec2, ad = 1.f - ed2;
    const float ma = 1.f - aa + 1e-10f, mb = 1.f - ab + 1e-10f;
    const float mc = 1.f - ac + 1e-10f, md = 1.f - ad + 1e-10f;
    const float q0 = ma, q1 = ma * mb, q2 = q1 * mc, q3 = q2 * md;
    float v = q3;
    #pragma unroll
    for (int off = 1; off < 32; off <<= 1) {
        float t = __shfl_up_sync(FULL, v, off);
        if (lane >= off) v *= t;
    }
    float E = __shfl_up_sync(FULL, v, 1);
    if (lane == 0) E = 1.f;
    const float wA = aa * E, wB = ab * E * q0, wC = ac * E * q1, wD = ad * E * q2;

    float SW = wA + wB + wC + wD;
    float SZ = wA * za + wB * zb + wC * zc + wD * zd;
    float SR = wA * cw[3 * p]     + wB * cw[3 * (p + 1)]     + wC * cw[3 * (p + 2)]     + wD * cw[3 * (p + 3)];
    float SG = wA * cw[3 * p + 1] + wB * cw[3 * (p + 1) + 1] + wC * cw[3 * (p + 2) + 1] + wD * cw[3 * (p + 3) + 1];
    float SB = wA * cw[3 * p + 2] + wB * cw[3 * (p + 1) + 2] + wC * cw[3 * (p + 2) + 2] + wD * cw[3 * (p + 3) + 2];

    #pragma unroll
    for (int off = 16; off; off >>= 1) {
        SW += __shfl_xor_sync(FULL, SW, off);
        SZ += __shfl_xor_sync(FULL, SZ, off);
        SR += __shfl_xor_sync(FULL, SR, off);
        SG += __shfl_xor_sync(FULL, SG, off);
        SB += __shfl_xor_sync(FULL, SB, off);
    }

    if (lane == 0) {
        orgb[ray * 3 + 0] = SR;
        orgb[ray * 3 + 1] = SG;
        orgb[ray * 3 + 2] = SB;
        const float* Tm = tform + bidx * 16;
        const float vz = dx * Tm[2] + dy * Tm[6] + dz * Tm[10];
        odep[ray] = -vz * SZ;
        omsk[ray] = SW;
    }
}

extern "C" void kernel_launch(void* const* d_in, const int* in_sizes, int n_in,
                              void* d_out, int out_size)
{
    const float* ro    = (const float*)d_in[0];
    const float* rdi   = (const float*)d_in[1];
    const float* tform = (const float*)d_in[2];
    const float* noise = (const float*)d_in[3];
    const float* usmp  = (const float*)d_in[4];
    const float* W1    = (const float*)d_in[5];
    const float* b1    = (const float*)d_in[6];
    const float* W2    = (const float*)d_in[7];
    const float* b2    = (const float*)d_in[8];

    float* out = (float*)d_out;
    float* orgb = out;
    float* odep = out + RAYS_TOTAL * 3;
    float* omsk = odep + RAYS_TOTAL;

    // 1) pack weights into staging buffer (device)
    pack_weights<<<1, 64>>>(W1, b1, W2, b2);
    // 2) staging -> __constant__ (D2D, graph-capturable)
    void* stage_addr = nullptr;
    cudaGetSymbolAddress(&stage_addr, g_stage);
    cudaMemcpyToSymbolAsync(cAll, stage_addr, sizeof(g_stage), 0,
                            cudaMemcpyDeviceToDevice, 0);
    // 3) main kernel
    dim3 grid(RAYS_TOTAL / RPB);
    dim3 block(RPB * 32);
    nerf_kernel<<<grid, block>>>(ro, rdi, tform, noise, usmp, orgb, odep, omsk);
}